// round 8
// baseline (speedup 1.0000x reference)
#include <cuda_runtime.h>
#include <cstdint>
#include <cstddef>

// Problem constants (match reference_code)
#define Cc 5
#define Hh 4096
#define Ww 4096
#define Nn 2000
#define PHh 64
#define PWw 64
#define MAXP 64   // max patches overlapping one 64x256 tile (mean ~5, Poisson)

// Load patch quad i of a 64-float row; zero if out of [0,16).
// Predicated load: no fetch when OOB, so no extra DRAM traffic.
__device__ __forceinline__ float4 ldq(const float* __restrict__ prow, int i) {
    float4 v = make_float4(0.f, 0.f, 0.f, 0.f);
    if ((unsigned)i < 16u) v = __ldg(reinterpret_cast<const float4*>(prow) + i);
    return v;
}

// Accumulate one patch into this thread's 16-row x 4-col register tile.
// A2 = (cx0 - pw0) & 3 is uniform per patch: element e of output quad comes
// from patch quad jA element (A2+e) if A2+e<4 else patch quad jA+1 element
// (A2+e-4). OOB patch quads read as zero, which exactly implements the
// left/right edge clipping.
template <int A2>
__device__ __forceinline__ void accum_patch(float4* acc,
                                            const float* __restrict__ pl,
                                            int py0, int jA) {
#pragma unroll
    for (int i = 0; i < 16; i++) {
        const int py = py0 + i;                 // patch row for this tile row
        if ((unsigned)py < 64u) {
            const float* prow = pl + (py << 6);
            const float4 A = ldq(prow, jA);
            if (A2 == 0) {
                acc[i].x += A.x; acc[i].y += A.y; acc[i].z += A.z; acc[i].w += A.w;
            } else {
                const float4 B = ldq(prow, jA + 1);
                if (A2 == 1) { acc[i].x += A.y; acc[i].y += A.z; acc[i].z += A.w; acc[i].w += B.x; }
                if (A2 == 2) { acc[i].x += A.z; acc[i].y += A.w; acc[i].z += B.x; acc[i].w += B.y; }
                if (A2 == 3) { acc[i].x += A.w; acc[i].y += B.x; acc[i].z += B.y; acc[i].w += B.z; }
            }
        }
    }
}

// One block per 64-col x 256-row output tile; all 5 bands looped inside so the
// patch-list scan is amortized. Thread (q = tid&15, r = tid>>4) owns quad
// column q of rows [ry0 + 16r, ry0 + 16r + 16). No atomics, no memset: every
// output element is written exactly once; accumulation order = patch index
// order = reference scan order (bitwise-deterministic).
__global__ __launch_bounds__(256, 2)
void gather_kernel(const float* __restrict__ patches,
                   const int*   __restrict__ positions,
                   float*       __restrict__ out) {
    __shared__ int  s_n[MAXP];
    __shared__ int2 s_pos[MAXP];
    __shared__ int  s_cnt;
    __shared__ int  s_woff[8];

    const int tid = threadIdx.x;
    const int cx0 = blockIdx.x << 6;   // tile col origin (64-wide)
    const int ry0 = blockIdx.y << 8;   // tile row origin (256-tall)

    if (tid == 0) s_cnt = 0;
    __syncthreads();

    // Ordered compaction: scan all N positions in 256-sized chunks; the
    // resulting list preserves ascending patch index (matches reference order).
    for (int base = 0; base < Nn; base += 256) {
        const int n = base + tid;
        bool pred = false;
        int2 pp = make_int2(0, 0);
        if (n < Nn) {
            pp = __ldg(reinterpret_cast<const int2*>(positions) + n);
            // pp.x = ph0 (row offset), pp.y = pw0 (col offset)
            pred = (pp.x > ry0 - PHh) && (pp.x < ry0 + 256) &&
                   (pp.y > cx0 - PWw) && (pp.y < cx0 + 64);
        }
        const unsigned m = __ballot_sync(0xffffffffu, pred);
        if ((tid & 31) == 0) s_woff[tid >> 5] = __popc(m);
        __syncthreads();
        if (tid == 0) {
            int acc = s_cnt;
#pragma unroll
            for (int w = 0; w < 8; w++) { int t = s_woff[w]; s_woff[w] = acc; acc += t; }
            s_cnt = acc;
        }
        __syncthreads();
        if (pred) {
            const int idx = s_woff[tid >> 5] + __popc(m & ((1u << (tid & 31)) - 1u));
            if (idx < MAXP) { s_n[idx] = n; s_pos[idx] = pp; }
        }
        __syncthreads();
    }
    const int k = min(s_cnt, MAXP);

    const int q = tid & 15;            // quad column within tile
    const int r = tid >> 4;            // 16-row group
    const int ybase = ry0 + (r << 4);

    for (int c = 0; c < Cc; c++) {
        float4 acc[16];
#pragma unroll
        for (int i = 0; i < 16; i++) acc[i] = make_float4(0.f, 0.f, 0.f, 0.f);

        for (int j = 0; j < k; j++) {
            const int ph0 = s_pos[j].x;
            const int pw0 = s_pos[j].y;
            const int py0 = ybase - ph0;            // patch row of tile row i=0
            if (py0 >= 64 || py0 <= -16) continue;  // no row overlap for this thread
            const int pb0 = cx0 - pw0;              // patch col of output col 0
            const int jA  = (pb0 >> 2) + q;         // arithmetic shift = floor
            if (jA > 15 || jA < -1) continue;       // no col overlap for this quad
            const int a2  = pb0 & 3;                // uniform shift per patch
            const float* pl = patches + (((size_t)s_n[j] * Cc + c) << 12);
            switch (a2) {
                case 0: accum_patch<0>(acc, pl, py0, jA); break;
                case 1: accum_patch<1>(acc, pl, py0, jA); break;
                case 2: accum_patch<2>(acc, pl, py0, jA); break;
                default: accum_patch<3>(acc, pl, py0, jA); break;
            }
        }

        // Coalesced writeout: warp = 16 consecutive quads x 2 rows per STG op.
        float* ob = out + (size_t)c * ((size_t)Hh * Ww);
#pragma unroll
        for (int i = 0; i < 16; i++) {
            *reinterpret_cast<float4*>(
                ob + (size_t)(ybase + i) * Ww + cx0 + (q << 2)) = acc[i];
        }
    }
}

extern "C" void kernel_launch(void* const* d_in, const int* in_sizes, int n_in,
                              void* d_out, int out_size) {
    // Inputs: patches (N*C*PH*PW f32), positions (N*2 i32) — identify by size.
    const float* patches;
    const int*   positions;
    if (in_sizes[0] == Nn * 2) {
        positions = (const int*)d_in[0];
        patches   = (const float*)d_in[1];
    } else {
        patches   = (const float*)d_in[0];
        positions = (const int*)d_in[1];
    }
    float* out = (float*)d_out;

    // Single kernel: writes the entire frame (zeros included), no memset needed.
    dim3 grid(Ww / 64, Hh / 256);
    gather_kernel<<<grid, 256, 0, 0>>>(patches, positions, out);
}

// round 9
// speedup vs baseline: 3.4851x; 3.4851x over previous
#include <cuda_runtime.h>
#include <cstdint>
#include <cstddef>

// Problem constants (match reference_code)
#define Cc 5
#define Hh 4096
#define Ww 4096
#define Nn 2000
#define PHh 64
#define PWw 64
#define TILES_X 64          // 4096 / 64
#define TILES_Y 64
#define NTILES (TILES_X * TILES_Y)
#define MAXP 32             // per-tile list capacity (mean ~1.9, Poisson)

// Scratch: per-tile patch lists (device globals — no allocation allowed).
__device__ int g_cnt[NTILES];
__device__ int g_list[NTILES * MAXP];

__global__ void zero_counts_kernel() {
    const int t = blockIdx.x * blockDim.x + threadIdx.x;
    if (t < NTILES) g_cnt[t] = 0;
}

// One thread per patch: append patch index to every overlapped 64x64 tile.
__global__ void bin_kernel(const int* __restrict__ positions) {
    const int n = blockIdx.x * blockDim.x + threadIdx.x;
    if (n >= Nn) return;
    const int2 pp = __ldg(reinterpret_cast<const int2*>(positions) + n);
    const int ty0 = pp.x >> 6, ty1 = (pp.x + PHh - 1) >> 6;   // row tiles
    const int tx0 = pp.y >> 6, tx1 = (pp.y + PWw - 1) >> 6;   // col tiles
    for (int ty = ty0; ty <= ty1; ty++)
        for (int tx = tx0; tx <= tx1; tx++) {
            const int t = ty * TILES_X + tx;
            const int s = atomicAdd(&g_cnt[t], 1);
            if (s < MAXP) g_list[t * MAXP + s] = n;
        }
}

// Load patch quad i of a 64-float row; zero if out of [0,16).
__device__ __forceinline__ float4 ldq(const float* __restrict__ prow, int i) {
    float4 v = make_float4(0.f, 0.f, 0.f, 0.f);
    if ((unsigned)i < 16u) v = __ldg(reinterpret_cast<const float4*>(prow) + i);
    return v;
}

// Accumulate one patch into this thread's 4-row x 4-col register tile.
// A2 = (cx0 - pw0) & 3, uniform per patch: output-quad element e comes from
// patch quad jA elem (A2+e) or patch quad jA+1 elem (A2+e-4). OOB quads read
// zero, which implements left/right edge clipping exactly.
template <int A2>
__device__ __forceinline__ void accum_patch(float4* acc,
                                            const float* __restrict__ pl,
                                            int py0, int jA) {
#pragma unroll
    for (int i = 0; i < 4; i++) {
        const int py = py0 + i;
        if ((unsigned)py < 64u) {
            const float* prow = pl + (py << 6);
            const float4 A = ldq(prow, jA);
            if (A2 == 0) {
                acc[i].x += A.x; acc[i].y += A.y; acc[i].z += A.z; acc[i].w += A.w;
            } else {
                const float4 B = ldq(prow, jA + 1);
                if (A2 == 1) { acc[i].x += A.y; acc[i].y += A.z; acc[i].z += A.w; acc[i].w += B.x; }
                if (A2 == 2) { acc[i].x += A.z; acc[i].y += A.w; acc[i].z += B.x; acc[i].w += B.y; }
                if (A2 == 3) { acc[i].x += A.w; acc[i].y += B.x; acc[i].z += B.y; acc[i].w += B.z; }
            }
        }
    }
}

// Block = one 64x64 output tile of one band (grid 64 x 64 x 5).
// Thread (q = tid&15, rr = tid>>4) owns quad column q of rows
// [ty*64 + rr*4, +4). No atomics in the hot path; each output pixel written
// exactly once, each patch pixel read exactly once (modulo edge quads).
__global__ __launch_bounds__(256)
void gather_kernel(const float* __restrict__ patches,
                   const int*   __restrict__ positions,
                   float*       __restrict__ out) {
    __shared__ int  s_n[MAXP];
    __shared__ int2 s_pos[MAXP];
    __shared__ int  s_k;

    const int tid = threadIdx.x;
    const int bx = blockIdx.x, by = blockIdx.y, c = blockIdx.z;
    const int tile = by * TILES_X + bx;
    const int cx0 = bx << 6;

    if (tid == 0) s_k = min(g_cnt[tile], MAXP);
    __syncthreads();
    const int k = s_k;

    if (tid < k) {
        const int n = g_list[tile * MAXP + tid];
        s_n[tid]   = n;
        s_pos[tid] = __ldg(reinterpret_cast<const int2*>(positions) + n);
    }
    __syncthreads();
    // Deterministic accumulation order: sort tiny list by patch index.
    if (tid == 0 && k > 1) {
        for (int a = 1; a < k; a++) {
            const int  vn = s_n[a];
            const int2 vp = s_pos[a];
            int b = a - 1;
            while (b >= 0 && s_n[b] > vn) {
                s_n[b + 1] = s_n[b]; s_pos[b + 1] = s_pos[b]; b--;
            }
            s_n[b + 1] = vn; s_pos[b + 1] = vp;
        }
    }
    __syncthreads();

    const int q  = tid & 15;                 // quad column (0..15)
    const int rr = tid >> 4;                 // 4-row group (0..15)
    const int y0 = (by << 6) + (rr << 2);    // first output row of this thread

    float4 acc[4];
#pragma unroll
    for (int i = 0; i < 4; i++) acc[i] = make_float4(0.f, 0.f, 0.f, 0.f);

    for (int j = 0; j < k; j++) {
        const int ph0 = s_pos[j].x;
        const int pw0 = s_pos[j].y;
        const int py0 = y0 - ph0;
        if (py0 >= 64 || py0 <= -4) continue;       // no row overlap
        const int pb0 = cx0 - pw0;
        const int jA  = (pb0 >> 2) + q;             // arithmetic shift = floor
        if (jA > 15 || jA < -1) continue;           // no col overlap
        const int a2  = pb0 & 3;
        const float* pl = patches + (((size_t)s_n[j] * Cc + c) << 12);
        switch (a2) {
            case 0: accum_patch<0>(acc, pl, py0, jA); break;
            case 1: accum_patch<1>(acc, pl, py0, jA); break;
            case 2: accum_patch<2>(acc, pl, py0, jA); break;
            default: accum_patch<3>(acc, pl, py0, jA); break;
        }
    }

    // Streaming stores: output is write-once, keep L2 for patch data.
    float* ob = out + (size_t)c * ((size_t)Hh * Ww);
#pragma unroll
    for (int i = 0; i < 4; i++) {
        __stcs(reinterpret_cast<float4*>(
                   ob + (size_t)(y0 + i) * Ww + cx0 + (q << 2)),
               acc[i]);
    }
}

extern "C" void kernel_launch(void* const* d_in, const int* in_sizes, int n_in,
                              void* d_out, int out_size) {
    const float* patches;
    const int*   positions;
    if (in_sizes[0] == Nn * 2) {
        positions = (const int*)d_in[0];
        patches   = (const float*)d_in[1];
    } else {
        patches   = (const float*)d_in[0];
        positions = (const int*)d_in[1];
    }
    float* out = (float*)d_out;

    zero_counts_kernel<<<(NTILES + 255) / 256, 256, 0, 0>>>();
    bin_kernel<<<(Nn + 255) / 256, 256, 0, 0>>>(positions);
    dim3 grid(TILES_X, TILES_Y, Cc);
    gather_kernel<<<grid, 256, 0, 0>>>(patches, positions, out);
}